// round 1
// baseline (speedup 1.0000x reference)
#include <cuda_runtime.h>

// Problem constants: B=1, T=4096, C=768, H=12, D=64
#define T_SEQ 4096
#define C_DIM 768
#define H_NUM 12
#define D_DIM 64

// Scratch (allocation-free: __device__ globals)
__device__ float g_q[H_NUM * D_DIM * T_SEQ];  // [h][d][t], pre-scaled by 1/8
__device__ float g_k[H_NUM * D_DIM * T_SEQ];  // [h][d][t]
__device__ float g_v[H_NUM * T_SEQ * D_DIM];  // [h][t][d]
__device__ float g_y[T_SEQ * C_DIM];          // [t][h*64+d]

// ---------------- packed f32x2 helpers ----------------
__device__ __forceinline__ unsigned long long pack2(float lo, float hi) {
    unsigned long long r;
    asm("mov.b64 %0, {%1,%2};" : "=l"(r) : "f"(lo), "f"(hi));
    return r;
}
__device__ __forceinline__ void unpack2(unsigned long long v, float& lo, float& hi) {
    asm("mov.b64 {%0,%1}, %2;" : "=f"(lo), "=f"(hi) : "l"(v));
}
__device__ __forceinline__ unsigned long long ffma2(unsigned long long a,
                                                    unsigned long long b,
                                                    unsigned long long c) {
    unsigned long long d;
    asm("fma.rn.f32x2 %0, %1, %2, %3;" : "=l"(d) : "l"(a), "l"(b), "l"(c));
    return d;
}
__device__ __forceinline__ unsigned long long mul2(unsigned long long a,
                                                   unsigned long long b) {
    unsigned long long d;
    asm("mul.rn.f32x2 %0, %1, %2;" : "=l"(d) : "l"(a), "l"(b));
    return d;
}

// ---------------- SGEMM: C = A[MxK] @ B[KxN] + bias ----------------
// MODE 0: epilogue scatters into g_q (scaled 1/8, [h][d][t]), g_k ([h][d][t]), g_v ([h][t][d])
// MODE 1: epilogue writes Cout[row*N+col] = acc + bias[col]
template <int MODE>
__global__ __launch_bounds__(256) void sgemm_kernel(
    const float* __restrict__ A, const float* __restrict__ B,
    const float* __restrict__ bias, float* __restrict__ Cout,
    int M, int N, int K) {
    __shared__ float As[16][132];  // [k][m], padded
    __shared__ float Bs[16][128];  // [k][n]

    const int tid = threadIdx.x;
    const int m0 = blockIdx.y * 128;
    const int n0 = blockIdx.x * 128;
    const int ty = tid / 16, tx = tid % 16;
    const int rowbase = ty * 8;

    unsigned long long acc[4][8];
#pragma unroll
    for (int i = 0; i < 4; i++)
#pragma unroll
        for (int j = 0; j < 8; j++) acc[i][j] = 0ull;

    const int ar = tid / 4, ac = tid % 4;   // A load: m = ar(+64), k = ac*4..+3
    const int br = tid / 32, bc = tid % 32; // B load: k = br(+8), n = bc*4..+3

    for (int k0 = 0; k0 < K; k0 += 16) {
#pragma unroll
        for (int p = 0; p < 2; p++) {
            int m = p * 64 + ar;
            float4 av = *(const float4*)&A[(size_t)(m0 + m) * K + k0 + ac * 4];
            As[ac * 4 + 0][m] = av.x;
            As[ac * 4 + 1][m] = av.y;
            As[ac * 4 + 2][m] = av.z;
            As[ac * 4 + 3][m] = av.w;
        }
#pragma unroll
        for (int p = 0; p < 2; p++) {
            int kk = p * 8 + br;
            *(float4*)&Bs[kk][bc * 4] =
                *(const float4*)&B[(size_t)(k0 + kk) * N + n0 + bc * 4];
        }
        __syncthreads();
#pragma unroll
        for (int k = 0; k < 16; k++) {
            ulonglong2 a01 = *(const ulonglong2*)&As[k][rowbase];
            ulonglong2 a23 = *(const ulonglong2*)&As[k][rowbase + 4];
            unsigned long long ap[4] = {a01.x, a01.y, a23.x, a23.y};
            float4 b0 = *(const float4*)&Bs[k][tx * 4];
            float4 b1 = *(const float4*)&Bs[k][64 + tx * 4];
            unsigned long long bb[8] = {
                pack2(b0.x, b0.x), pack2(b0.y, b0.y), pack2(b0.z, b0.z), pack2(b0.w, b0.w),
                pack2(b1.x, b1.x), pack2(b1.y, b1.y), pack2(b1.z, b1.z), pack2(b1.w, b1.w)};
#pragma unroll
            for (int i = 0; i < 4; i++)
#pragma unroll
                for (int j = 0; j < 8; j++)
                    acc[i][j] = ffma2(ap[i], bb[j], acc[i][j]);
        }
        __syncthreads();
    }

    // epilogue
#pragma unroll
    for (int i = 0; i < 4; i++) {
        float lo[8], hi[8];
#pragma unroll
        for (int j = 0; j < 8; j++) unpack2(acc[i][j], lo[j], hi[j]);
        int r0 = m0 + rowbase + 2 * i;  // rows r0 (lo) and r0+1 (hi)
        if (MODE == 1) {
            int c0 = n0 + tx * 4;
            int c1 = n0 + 64 + tx * 4;
            float b00 = bias[c0], b01 = bias[c0 + 1], b02 = bias[c0 + 2], b03 = bias[c0 + 3];
            float b10 = bias[c1], b11 = bias[c1 + 1], b12 = bias[c1 + 2], b13 = bias[c1 + 3];
            float4 v;
            v.x = lo[0] + b00; v.y = lo[1] + b01; v.z = lo[2] + b02; v.w = lo[3] + b03;
            *(float4*)&Cout[(size_t)r0 * N + c0] = v;
            v.x = lo[4] + b10; v.y = lo[5] + b11; v.z = lo[6] + b12; v.w = lo[7] + b13;
            *(float4*)&Cout[(size_t)r0 * N + c1] = v;
            v.x = hi[0] + b00; v.y = hi[1] + b01; v.z = hi[2] + b02; v.w = hi[3] + b03;
            *(float4*)&Cout[(size_t)(r0 + 1) * N + c0] = v;
            v.x = hi[4] + b10; v.y = hi[5] + b11; v.z = hi[6] + b12; v.w = hi[7] + b13;
            *(float4*)&Cout[(size_t)(r0 + 1) * N + c1] = v;
        } else {
#pragma unroll
            for (int j = 0; j < 8; j++) {
                int col = (j < 4) ? (n0 + tx * 4 + j) : (n0 + 64 + tx * 4 + (j - 4));
                float bv = bias[col];
                int which = col / C_DIM;
                int c = col % C_DIM;
                int h = c >> 6, dd = c & 63;
#pragma unroll
                for (int half = 0; half < 2; half++) {
                    int row = r0 + half;
                    float val = ((half == 0) ? lo[j] : hi[j]) + bv;
                    if (which == 0) {
                        g_q[(size_t)(h * D_DIM + dd) * T_SEQ + row] = val * 0.125f;
                    } else if (which == 1) {
                        g_k[(size_t)(h * D_DIM + dd) * T_SEQ + row] = val;
                    } else {
                        g_v[(size_t)(h * T_SEQ + row) * D_DIM + dd] = val;
                    }
                }
            }
        }
    }
}

// ---------------- Flash attention (causal), 64x64 tiles ----------------
// Block b handles q-blocks b and 63-b for head blockIdx.y -> 65 tile-units each.
__global__ __launch_bounds__(256) void flash_kernel() {
    __shared__ float Qs[64 * 64];   // [d][m]
    __shared__ float KPs[64 * 64];  // K as [d][n]; later P as [m][n]
    __shared__ float Vs[64 * 64];   // [n][dv]

    const int tid = threadIdx.x;
    const int h = blockIdx.y;
    const int ty = tid / 16, tx = tid % 16;
    const int lr = tid / 16, lq = tid % 16;  // load mapping

#pragma unroll 1
    for (int pass = 0; pass < 2; pass++) {
        const int qb = (pass == 0) ? (int)blockIdx.x : 63 - (int)blockIdx.x;
        const int qm0 = qb * 64;

        __syncthreads();
#pragma unroll
        for (int p = 0; p < 4; p++) {
            int d = p * 16 + lr;
            *(float4*)&Qs[d * 64 + lq * 4] =
                *(const float4*)&g_q[(size_t)(h * D_DIM + d) * T_SEQ + qm0 + lq * 4];
        }

        float mi[4], li[4];
        unsigned long long o2[4][2];
#pragma unroll
        for (int i = 0; i < 4; i++) {
            mi[i] = -1e30f;
            li[i] = 0.0f;
            o2[i][0] = 0ull;
            o2[i][1] = 0ull;
        }

#pragma unroll 1
        for (int j = 0; j <= qb; j++) {
            const int kv0 = j * 64;
            __syncthreads();
#pragma unroll
            for (int p = 0; p < 4; p++) {
                int d = p * 16 + lr;
                *(float4*)&KPs[d * 64 + lq * 4] =
                    *(const float4*)&g_k[(size_t)(h * D_DIM + d) * T_SEQ + kv0 + lq * 4];
            }
#pragma unroll
            for (int p = 0; p < 4; p++) {
                int n = p * 16 + lr;
                *(float4*)&Vs[n * 64 + lq * 4] =
                    *(const float4*)&g_v[(size_t)(h * T_SEQ + kv0 + n) * D_DIM + lq * 4];
            }
            __syncthreads();

            // GEMM1: S = Q^T-tile . K-tile, rows ty*4..+3, cols tx*4..+3
            unsigned long long s2[2][4];
#pragma unroll
            for (int mp = 0; mp < 2; mp++)
#pragma unroll
                for (int jj = 0; jj < 4; jj++) s2[mp][jj] = 0ull;
#pragma unroll 16
            for (int d = 0; d < 64; d++) {
                ulonglong2 qv = *(const ulonglong2*)&Qs[d * 64 + ty * 4];
                float4 kv = *(const float4*)&KPs[d * 64 + tx * 4];
                unsigned long long kb[4] = {pack2(kv.x, kv.x), pack2(kv.y, kv.y),
                                            pack2(kv.z, kv.z), pack2(kv.w, kv.w)};
#pragma unroll
                for (int jj = 0; jj < 4; jj++) {
                    s2[0][jj] = ffma2(qv.x, kb[jj], s2[0][jj]);
                    s2[1][jj] = ffma2(qv.y, kb[jj], s2[1][jj]);
                }
            }
            float s[4][4];
#pragma unroll
            for (int jj = 0; jj < 4; jj++) {
                unpack2(s2[0][jj], s[0][jj], s[1][jj]);
                unpack2(s2[1][jj], s[2][jj], s[3][jj]);
            }

            if (j == qb) {  // causal mask on diagonal block
#pragma unroll
                for (int i = 0; i < 4; i++)
#pragma unroll
                    for (int jj = 0; jj < 4; jj++)
                        if (tx * 4 + jj > ty * 4 + i) s[i][jj] = -1e30f;
            }

            // online softmax (rows spread over 16 lanes: shfl_xor 1,2,4,8)
#pragma unroll
            for (int i = 0; i < 4; i++) {
                float rm = fmaxf(fmaxf(s[i][0], s[i][1]), fmaxf(s[i][2], s[i][3]));
#pragma unroll
                for (int off = 8; off >= 1; off >>= 1)
                    rm = fmaxf(rm, __shfl_xor_sync(0xffffffffu, rm, off));
                float mnew = fmaxf(mi[i], rm);
                float alpha = __expf(mi[i] - mnew);
                mi[i] = mnew;
                float rs = 0.0f;
#pragma unroll
                for (int jj = 0; jj < 4; jj++) {
                    float p = __expf(s[i][jj] - mnew);
                    s[i][jj] = p;
                    rs += p;
                }
#pragma unroll
                for (int off = 8; off >= 1; off >>= 1)
                    rs += __shfl_xor_sync(0xffffffffu, rs, off);
                li[i] = li[i] * alpha + rs;
                unsigned long long a2 = pack2(alpha, alpha);
                o2[i][0] = mul2(o2[i][0], a2);
                o2[i][1] = mul2(o2[i][1], a2);
            }

            __syncthreads();  // everyone done reading KPs as K
#pragma unroll
            for (int i = 0; i < 4; i++) {
                float4 pv = make_float4(s[i][0], s[i][1], s[i][2], s[i][3]);
                *(float4*)&KPs[(ty * 4 + i) * 64 + tx * 4] = pv;  // P as [m][n]
            }
            __syncthreads();

            // GEMM2: O += P . V, rows ty*4..+3, dv cols tx*4..+3
#pragma unroll 16
            for (int n = 0; n < 64; n++) {
                ulonglong2 vv = *(const ulonglong2*)&Vs[n * 64 + tx * 4];
#pragma unroll
                for (int i = 0; i < 4; i++) {
                    float pi = KPs[(ty * 4 + i) * 64 + n];
                    unsigned long long pb = pack2(pi, pi);
                    o2[i][0] = ffma2(pb, vv.x, o2[i][0]);
                    o2[i][1] = ffma2(pb, vv.y, o2[i][1]);
                }
            }
        }

        // normalize + write y[t][h*64+dv]
#pragma unroll
        for (int i = 0; i < 4; i++) {
            float inv = 1.0f / li[i];
            float a, b, c, d;
            unpack2(o2[i][0], a, b);
            unpack2(o2[i][1], c, d);
            float4 ov = make_float4(a * inv, b * inv, c * inv, d * inv);
            *(float4*)&g_y[(size_t)(qm0 + ty * 4 + i) * C_DIM + h * 64 + tx * 4] = ov;
        }
    }
}

// ---------------- launch ----------------
extern "C" void kernel_launch(void* const* d_in, const int* in_sizes, int n_in,
                              void* d_out, int out_size) {
    const float* x = (const float*)d_in[0];
    // d_in[1] = mask (ignored: causality is hardcoded)
    const float* Wqkv = (const float*)d_in[2];
    const float* bqkv = (const float*)d_in[3];
    const float* Wproj = (const float*)d_in[4];
    const float* bproj = (const float*)d_in[5];
    float* out = (float*)d_out;

    void* yptr = nullptr;
    cudaGetSymbolAddress(&yptr, g_y);

    // 1) QKV projection with scatter epilogue
    sgemm_kernel<0><<<dim3(18, 32), 256>>>(x, Wqkv, bqkv, nullptr,
                                           T_SEQ, 3 * C_DIM, C_DIM);
    // 2) causal flash attention
    flash_kernel<<<dim3(32, H_NUM), 256>>>();
    // 3) output projection
    sgemm_kernel<1><<<dim3(6, 32), 256>>>((const float*)yptr, Wproj, bproj, out,
                                          T_SEQ, C_DIM, C_DIM);
}